// round 2
// baseline (speedup 1.0000x reference)
#include <cuda_runtime.h>
#include <cuda_bf16.h>
#include <stdint.h>

#define N_NODES_MAX 100000
#define E_MAX       3200000
#define F           128

// ---------------- device scratch (static allocation only) ----------------
__device__ int   g_is64;
__device__ int   g_deg[N_NODES_MAX];
__device__ float g_dinv[N_NODES_MAX];
__device__ int   g_rowptr[N_NODES_MAX + 1];
__device__ int   g_cursor[N_NODES_MAX];
__device__ int   g_adj[E_MAX];
__device__ int   g_bsums[256];
__device__ int   g_bscan[256];
__device__ float g_s[(size_t)N_NODES_MAX * F];   // dinv-scaled support, 51.2 MB

// ---------------- 0. detect edge_index dtype (int32 vs int64) ----------------
// int64 indices < 2^17: every odd 32-bit word is 0. int32 random indices:
// probability all 2048 odd words are 0 is ~0.
__global__ void detect_kernel(const unsigned int* __restrict__ raw) {
    __shared__ int nonzero;
    if (threadIdx.x == 0) nonzero = 0;
    __syncthreads();
    int local = 0;
    for (int i = threadIdx.x; i < 2048; i += blockDim.x)
        if (raw[2 * i + 1] != 0u) local = 1;
    if (local) atomicOr(&nonzero, 1);
    __syncthreads();
    if (threadIdx.x == 0) g_is64 = (nonzero == 0) ? 1 : 0;
}

__device__ __forceinline__ int get_idx(const void* ei, size_t pos) {
    if (g_is64) return (int)((const long long*)ei)[pos];
    return ((const int*)ei)[pos];
}

// ---------------- 1. degree ----------------
__global__ void init_deg_kernel(int n) {
    int i = blockIdx.x * blockDim.x + threadIdx.x;
    if (i < n) g_deg[i] = 1;   // self loop
}

__global__ void degree_kernel(const void* __restrict__ ei, int e) {
    int i = blockIdx.x * blockDim.x + threadIdx.x;
    if (i < e) atomicAdd(&g_deg[get_idx(ei, i)], 1);
}

__global__ void dinv_kernel(int n) {
    int i = blockIdx.x * blockDim.x + threadIdx.x;
    if (i < n) g_dinv[i] = rsqrtf((float)g_deg[i]);
}

// ---------------- 2. CSR build: scan of (deg-1) ----------------
// per-block exclusive scan over 1024 elements (256 thr x 4)
__global__ void scan_local_kernel(int n) {
    __shared__ int wsum[8];
    int tid  = threadIdx.x;
    int base = blockIdx.x * 1024 + tid * 4;
    int v[4];
#pragma unroll
    for (int j = 0; j < 4; j++) {
        int idx = base + j;
        v[j] = (idx < n) ? (g_deg[idx] - 1) : 0;
    }
    int s = v[0] + v[1] + v[2] + v[3];
    int x = s;
#pragma unroll
    for (int o = 1; o < 32; o <<= 1) {
        int y = __shfl_up_sync(0xffffffffu, x, o);
        if ((tid & 31) >= o) x += y;
    }
    if ((tid & 31) == 31) wsum[tid >> 5] = x;
    __syncthreads();
    if (tid < 8) {
        int w = wsum[tid];
#pragma unroll
        for (int o = 1; o < 8; o <<= 1) {
            int y = __shfl_up_sync(0xffu, w, o);
            if (tid >= o) w += y;
        }
        wsum[tid] = w;  // inclusive warp sums
    }
    __syncthreads();
    int excl = x - s + ((tid >= 32) ? wsum[(tid >> 5) - 1] : 0);
    int run = excl;
#pragma unroll
    for (int j = 0; j < 4; j++) {
        int idx = base + j;
        if (idx < n) g_rowptr[idx] = run;
        run += v[j];
    }
    if (tid == 255) g_bsums[blockIdx.x] = run;  // block total
}

// single-block scan of block sums (nb <= 128)
__global__ void scan_bsums_kernel(int nb) {
    __shared__ int sh[128];
    int tid = threadIdx.x;
    int v = (tid < nb) ? g_bsums[tid] : 0;
    sh[tid] = v;
    __syncthreads();
#pragma unroll
    for (int o = 1; o < 128; o <<= 1) {
        int t = sh[tid];
        int y = (tid >= o) ? sh[tid - o] : 0;
        __syncthreads();
        sh[tid] = t + y;
        __syncthreads();
    }
    g_bscan[tid] = sh[tid] - v;  // exclusive
}

__global__ void add_offsets_kernel(int n, int e) {
    int i = blockIdx.x * blockDim.x + threadIdx.x;
    if (i < n) {
        int r = g_rowptr[i] + g_bscan[i >> 10];
        g_rowptr[i] = r;
        g_cursor[i] = r;
    }
    if (i == 0) g_rowptr[n] = e;
}

__global__ void scatter_kernel(const void* __restrict__ ei, int e) {
    int i = blockIdx.x * blockDim.x + threadIdx.x;
    if (i < e) {
        int src = get_idx(ei, i);
        int dst = get_idx(ei, (size_t)e + i);
        int pos = atomicAdd(&g_cursor[src], 1);
        g_adj[pos] = dst;
    }
}

// ---------------- 3. SGEMM: s = (x @ W) * dinv[row] ----------------
// 128x128 tile, 256 threads, 8x8 per thread, K-tile 16.
__global__ __launch_bounds__(256, 2) void gemm_kernel(
    const float* __restrict__ x, const float* __restrict__ w, int n)
{
    __shared__ float As[16][128];  // x tile, transposed
    __shared__ float Bs[16][128];  // w tile

    int tid = threadIdx.x;
    int block_row = blockIdx.x * 128;
    int tx = tid & 15;   // 0..15  (col group of 8)
    int ty = tid >> 4;   // 0..15  (row group of 8)

    float acc[8][8];
#pragma unroll
    for (int i = 0; i < 8; i++)
#pragma unroll
        for (int j = 0; j < 8; j++) acc[i][j] = 0.0f;

    int lr = tid >> 2;          // 0..63
    int lc = (tid & 3) * 4;     // 0,4,8,12
    int wr = tid >> 5;          // 0..7
    int wc = (tid & 31) * 4;    // 0..124

    for (int k0 = 0; k0 < F; k0 += 16) {
        // load x tile (128 rows x 16 cols), store transposed
#pragma unroll
        for (int h = 0; h < 2; h++) {
            int r  = lr + h * 64;
            int gr = block_row + r;
            float4 v = make_float4(0.f, 0.f, 0.f, 0.f);
            if (gr < n) v = *(const float4*)(x + (size_t)gr * F + k0 + lc);
            As[lc + 0][r] = v.x;
            As[lc + 1][r] = v.y;
            As[lc + 2][r] = v.z;
            As[lc + 3][r] = v.w;
        }
        // load w tile (16 rows x 128 cols)
#pragma unroll
        for (int h = 0; h < 2; h++) {
            int r = wr + h * 8;
            float4 v = *(const float4*)(w + (size_t)(k0 + r) * F + wc);
            *(float4*)(&Bs[r][wc]) = v;
        }
        __syncthreads();

#pragma unroll
        for (int k = 0; k < 16; k++) {
            float a[8], b[8];
            *(float4*)(&a[0]) = *(const float4*)(&As[k][ty * 8 + 0]);
            *(float4*)(&a[4]) = *(const float4*)(&As[k][ty * 8 + 4]);
            *(float4*)(&b[0]) = *(const float4*)(&Bs[k][tx * 8 + 0]);
            *(float4*)(&b[4]) = *(const float4*)(&Bs[k][tx * 8 + 4]);
#pragma unroll
            for (int i = 0; i < 8; i++)
#pragma unroll
                for (int j = 0; j < 8; j++)
                    acc[i][j] += a[i] * b[j];
        }
        __syncthreads();
    }

    // epilogue: scale row by dinv and write to g_s
#pragma unroll
    for (int i = 0; i < 8; i++) {
        int gr = block_row + ty * 8 + i;
        if (gr < n) {
            float d = g_dinv[gr];
#pragma unroll
            for (int j = 0; j < 8; j += 4) {
                float4 v;
                v.x = acc[i][j + 0] * d;
                v.y = acc[i][j + 1] * d;
                v.z = acc[i][j + 2] * d;
                v.w = acc[i][j + 3] * d;
                *(float4*)(g_s + (size_t)gr * F + tx * 8 + j) = v;
            }
        }
    }
}

// ---------------- 4. aggregation: one warp per node ----------------
__global__ void aggregate_kernel(float* __restrict__ out,
                                 const float* __restrict__ bias, int n)
{
    int warp = (blockIdx.x * blockDim.x + threadIdx.x) >> 5;
    int lane = threadIdx.x & 31;
    if (warp >= n) return;

    const float4* sv = (const float4*)g_s;

    // self loop: init with own scaled-support row
    float4 acc = sv[(size_t)warp * 32 + lane];

    int j   = g_rowptr[warp];
    int end = g_rowptr[warp + 1];

    // unroll by 4 for MLP
    for (; j + 3 < end; j += 4) {
        int c0 = g_adj[j + 0];
        int c1 = g_adj[j + 1];
        int c2 = g_adj[j + 2];
        int c3 = g_adj[j + 3];
        float4 v0 = sv[(size_t)c0 * 32 + lane];
        float4 v1 = sv[(size_t)c1 * 32 + lane];
        float4 v2 = sv[(size_t)c2 * 32 + lane];
        float4 v3 = sv[(size_t)c3 * 32 + lane];
        acc.x += (v0.x + v1.x) + (v2.x + v3.x);
        acc.y += (v0.y + v1.y) + (v2.y + v3.y);
        acc.z += (v0.z + v1.z) + (v2.z + v3.z);
        acc.w += (v0.w + v1.w) + (v2.w + v3.w);
    }
    for (; j < end; j++) {
        int c = g_adj[j];
        float4 v = sv[(size_t)c * 32 + lane];
        acc.x += v.x; acc.y += v.y; acc.z += v.z; acc.w += v.w;
    }

    float d  = g_dinv[warp];
    float4 b = ((const float4*)bias)[lane];
    float4 o;
    o.x = acc.x * d + b.x;
    o.y = acc.y * d + b.y;
    o.z = acc.z * d + b.z;
    o.w = acc.w * d + b.w;
    ((float4*)out)[(size_t)warp * 32 + lane] = o;
}

// ---------------- launch ----------------
extern "C" void kernel_launch(void* const* d_in, const int* in_sizes, int n_in,
                              void* d_out, int out_size)
{
    const float* x    = (const float*)d_in[0];
    const void*  ei   = d_in[1];
    const float* w    = (const float*)d_in[2];
    const float* bias = (const float*)d_in[3];
    float*       out  = (float*)d_out;

    int n = in_sizes[0] / F;     // nodes
    int e = in_sizes[1] / 2;     // edges

    int nb = (n + 1023) / 1024;  // scan blocks (<=128 for n<=131072)

    detect_kernel<<<1, 256>>>((const unsigned int*)ei);

    init_deg_kernel<<<(n + 255) / 256, 256>>>(n);
    degree_kernel<<<(e + 255) / 256, 256>>>(ei, e);
    dinv_kernel<<<(n + 255) / 256, 256>>>(n);

    scan_local_kernel<<<nb, 256>>>(n);
    scan_bsums_kernel<<<1, 128>>>(nb);
    add_offsets_kernel<<<(n + 255) / 256, 256>>>(n, e);
    scatter_kernel<<<(e + 255) / 256, 256>>>(ei, e);

    gemm_kernel<<<(n + 127) / 128, 256>>>(x, w, n);

    int agg_blocks = (n * 32 + 255) / 256;
    aggregate_kernel<<<agg_blocks, 256>>>(out, bias, n);
}

// round 4
// speedup vs baseline: 1.1728x; 1.1728x over previous
#include <cuda_runtime.h>
#include <cuda_fp16.h>
#include <mma.h>
#include <stdint.h>

using namespace nvcuda;

#define N_NODES_MAX 100000
#define E_MAX       3200000
#define F           128

// ---------------- device scratch (static allocation only) ----------------
__device__ int   g_is64;
__device__ int   g_deg[N_NODES_MAX];
__device__ float g_dinv[N_NODES_MAX];
__device__ int   g_rowptr[N_NODES_MAX + 1];
__device__ int   g_cursor[N_NODES_MAX];
__device__ int   g_adj[E_MAX];
__device__ int   g_bsums[256];
__device__ int   g_bscan[256];
__device__ __half2 g_sh[(size_t)N_NODES_MAX * 64];  // fp16 scaled support, 25.6 MB

// ---------------- 0. detect edge_index dtype (int32 vs int64) ----------------
__global__ void detect_kernel(const unsigned int* __restrict__ raw) {
    __shared__ int nonzero;
    if (threadIdx.x == 0) nonzero = 0;
    __syncthreads();
    int local = 0;
    for (int i = threadIdx.x; i < 2048; i += blockDim.x)
        if (raw[2 * i + 1] != 0u) local = 1;
    if (local) atomicOr(&nonzero, 1);
    __syncthreads();
    if (threadIdx.x == 0) g_is64 = (nonzero == 0) ? 1 : 0;
}

__device__ __forceinline__ int get_idx(const void* ei, size_t pos) {
    if (g_is64) return (int)((const long long*)ei)[pos];
    return ((const int*)ei)[pos];
}

// ---------------- 1. degree ----------------
__global__ void init_deg_kernel(int n) {
    int i = blockIdx.x * blockDim.x + threadIdx.x;
    if (i < n) g_deg[i] = 1;   // self loop
}

__global__ void degree_kernel(const void* __restrict__ ei, int e) {
    int i = blockIdx.x * blockDim.x + threadIdx.x;
    if (i < e) atomicAdd(&g_deg[get_idx(ei, i)], 1);
}

// ---------------- 2. CSR build: scan of (deg-1), also computes dinv ---------
__global__ void scan_local_kernel(int n) {
    __shared__ int wsum[8];
    int tid  = threadIdx.x;
    int base = blockIdx.x * 1024 + tid * 4;
    int v[4];
#pragma unroll
    for (int j = 0; j < 4; j++) {
        int idx = base + j;
        if (idx < n) {
            int d = g_deg[idx];
            v[j] = d - 1;
            g_dinv[idx] = rsqrtf((float)d);
        } else v[j] = 0;
    }
    int s = v[0] + v[1] + v[2] + v[3];
    int x = s;
#pragma unroll
    for (int o = 1; o < 32; o <<= 1) {
        int y = __shfl_up_sync(0xffffffffu, x, o);
        if ((tid & 31) >= o) x += y;
    }
    if ((tid & 31) == 31) wsum[tid >> 5] = x;
    __syncthreads();
    if (tid < 8) {
        int w = wsum[tid];
#pragma unroll
        for (int o = 1; o < 8; o <<= 1) {
            int y = __shfl_up_sync(0xffu, w, o);
            if (tid >= o) w += y;
        }
        wsum[tid] = w;
    }
    __syncthreads();
    int excl = x - s + ((tid >= 32) ? wsum[(tid >> 5) - 1] : 0);
    int run = excl;
#pragma unroll
    for (int j = 0; j < 4; j++) {
        int idx = base + j;
        if (idx < n) g_rowptr[idx] = run;
        run += v[j];
    }
    if (tid == 255) g_bsums[blockIdx.x] = run;
}

__global__ void scan_bsums_kernel(int nb) {
    __shared__ int sh[128];
    int tid = threadIdx.x;
    int v = (tid < nb) ? g_bsums[tid] : 0;
    sh[tid] = v;
    __syncthreads();
#pragma unroll
    for (int o = 1; o < 128; o <<= 1) {
        int t = sh[tid];
        int y = (tid >= o) ? sh[tid - o] : 0;
        __syncthreads();
        sh[tid] = t + y;
        __syncthreads();
    }
    g_bscan[tid] = sh[tid] - v;
}

__global__ void add_offsets_kernel(int n, int e) {
    int i = blockIdx.x * blockDim.x + threadIdx.x;
    if (i < n) {
        int r = g_rowptr[i] + g_bscan[i >> 10];
        g_rowptr[i] = r;
        g_cursor[i] = r;
    }
    if (i == 0) g_rowptr[n] = e;
}

__global__ void scatter_kernel(const void* __restrict__ ei, int e) {
    int i = blockIdx.x * blockDim.x + threadIdx.x;
    if (i < e) {
        int src = get_idx(ei, i);
        int dst = get_idx(ei, (size_t)e + i);
        int pos = atomicAdd(&g_cursor[src], 1);
        g_adj[pos] = dst;
    }
}

// ---------------- 3. tensor-core GEMM: s = fp16((x @ W) * dinv[row]) --------
// x split into hi+lo fp16 (two passes) to kill input-rounding error.
// Block: 128x128 tile, 256 threads (8 warps, each 32x64 of output).
#define APAD 136   // half stride with padding

__global__ __launch_bounds__(256) void gemm_tc_kernel(
    const float* __restrict__ x, const float* __restrict__ w, int n)
{
    extern __shared__ char smem[];
    __half* Ahi = (__half*)smem;                 // [128][APAD]
    __half* Alo = Ahi + 128 * APAD;
    __half* Bs  = Alo + 128 * APAD;
    float*  Cs  = (float*)smem;                  // epilogue reuse [128][APAD]

    int tid = threadIdx.x;
    int block_row = blockIdx.x * 128;
    int wid  = tid >> 5;
    int wm   = wid & 3;     // 0..3 -> M offset wm*32
    int wn   = wid >> 2;    // 0..1 -> N offset wn*64

    // load + convert: 256 threads cover 128 rows x 128 cols (float4 each)
    int c4 = (tid & 31) * 4;    // col
    int r0 = tid >> 5;          // 0..7
#pragma unroll
    for (int i = 0; i < 16; i++) {
        int r  = r0 + i * 8;    // 0..127, each exactly once
        int gr = block_row + r;
        float4 v = make_float4(0.f, 0.f, 0.f, 0.f);
        if (gr < n) v = *(const float4*)(x + (size_t)gr * F + c4);
        __half h0 = __float2half_rn(v.x), h1 = __float2half_rn(v.y);
        __half h2 = __float2half_rn(v.z), h3 = __float2half_rn(v.w);
        Ahi[r * APAD + c4 + 0] = h0;
        Ahi[r * APAD + c4 + 1] = h1;
        Ahi[r * APAD + c4 + 2] = h2;
        Ahi[r * APAD + c4 + 3] = h3;
        Alo[r * APAD + c4 + 0] = __float2half_rn(v.x - __half2float(h0));
        Alo[r * APAD + c4 + 1] = __float2half_rn(v.y - __half2float(h1));
        Alo[r * APAD + c4 + 2] = __float2half_rn(v.z - __half2float(h2));
        Alo[r * APAD + c4 + 3] = __float2half_rn(v.w - __half2float(h3));
        // W tile: row r (0..127), single fp16
        float4 wv = *(const float4*)(w + (size_t)r * F + c4);
        Bs[r * APAD + c4 + 0] = __float2half_rn(wv.x);
        Bs[r * APAD + c4 + 1] = __float2half_rn(wv.y);
        Bs[r * APAD + c4 + 2] = __float2half_rn(wv.z);
        Bs[r * APAD + c4 + 3] = __float2half_rn(wv.w);
    }
    __syncthreads();

    wmma::fragment<wmma::accumulator, 16, 16, 16, float> acc[2][4];
#pragma unroll
    for (int mi = 0; mi < 2; mi++)
#pragma unroll
        for (int ni = 0; ni < 4; ni++) wmma::fill_fragment(acc[mi][ni], 0.0f);

#pragma unroll
    for (int k = 0; k < 8; k++) {
        wmma::fragment<wmma::matrix_b, 16, 16, 16, __half, wmma::row_major> bf[4];
#pragma unroll
        for (int ni = 0; ni < 4; ni++)
            wmma::load_matrix_sync(bf[ni], Bs + (k * 16) * APAD + wn * 64 + ni * 16, APAD);
#pragma unroll
        for (int pass = 0; pass < 2; pass++) {
            const __half* A = pass ? Alo : Ahi;
            wmma::fragment<wmma::matrix_a, 16, 16, 16, __half, wmma::row_major> af[2];
#pragma unroll
            for (int mi = 0; mi < 2; mi++)
                wmma::load_matrix_sync(af[mi], A + (wm * 32 + mi * 16) * APAD + k * 16, APAD);
#pragma unroll
            for (int mi = 0; mi < 2; mi++)
#pragma unroll
                for (int ni = 0; ni < 4; ni++)
                    wmma::mma_sync(acc[mi][ni], af[mi], bf[ni], acc[mi][ni]);
        }
    }
    __syncthreads();   // done reading A/B smem; reuse as float C

#pragma unroll
    for (int mi = 0; mi < 2; mi++)
#pragma unroll
        for (int ni = 0; ni < 4; ni++)
            wmma::store_matrix_sync(Cs + (wm * 32 + mi * 16) * APAD + wn * 64 + ni * 16,
                                    acc[mi][ni], APAD, wmma::mem_row_major);
    __syncthreads();

    // scale by dinv, convert to fp16, write g_sh
    int r  = tid >> 1;              // 0..127
    int cb = (tid & 1) * 64;        // col base 0 or 64
    int gr = block_row + r;
    if (gr < n) {
        float d = g_dinv[gr];
        const float* crow = Cs + r * APAD + cb;
        __half2* orow = g_sh + (size_t)gr * 64 + cb / 2;
#pragma unroll
        for (int j = 0; j < 64; j += 2)
            orow[j >> 1] = __floats2half2_rn(crow[j] * d, crow[j + 1] * d);
    }
}

// ---------------- 4. aggregation: one warp per node, fp16 gather ------------
__global__ void aggregate_kernel(float* __restrict__ out,
                                 const float* __restrict__ bias, int n)
{
    int warp = (blockIdx.x * blockDim.x + threadIdx.x) >> 5;
    int lane = threadIdx.x & 31;
    if (warp >= n) return;

    const uint2* sv = (const uint2*)g_sh;   // row = 32 uint2 (256 B)

    uint2 p = __ldg(&sv[(size_t)warp * 32 + lane]);   // self loop
    __half2 a0 = *(__half2*)&p.x, a1 = *(__half2*)&p.y;
    float2 f0 = __half22float2(a0), f1 = __half22float2(a1);
    float4 acc = make_float4(f0.x, f0.y, f1.x, f1.y);

    int j   = g_rowptr[warp];
    int end = g_rowptr[warp + 1];

    for (; j + 3 < end; j += 4) {
        int c0 = g_adj[j + 0];
        int c1 = g_adj[j + 1];
        int c2 = g_adj[j + 2];
        int c3 = g_adj[j + 3];
        uint2 p0 = __ldg(&sv[(size_t)c0 * 32 + lane]);
        uint2 p1 = __ldg(&sv[(size_t)c1 * 32 + lane]);
        uint2 p2 = __ldg(&sv[(size_t)c2 * 32 + lane]);
        uint2 p3 = __ldg(&sv[(size_t)c3 * 32 + lane]);
        float2 q0 = __half22float2(*(__half2*)&p0.x), q1 = __half22float2(*(__half2*)&p0.y);
        float2 q2 = __half22float2(*(__half2*)&p1.x), q3 = __half22float2(*(__half2*)&p1.y);
        float2 q4 = __half22float2(*(__half2*)&p2.x), q5 = __half22float2(*(__half2*)&p2.y);
        float2 q6 = __half22float2(*(__half2*)&p3.x), q7 = __half22float2(*(__half2*)&p3.y);
        acc.x += (q0.x + q2.x) + (q4.x + q6.x);
        acc.y += (q0.y + q2.y) + (q4.y + q6.y);
        acc.z += (q1.x + q3.x) + (q5.x + q7.x);
        acc.w += (q1.y + q3.y) + (q5.y + q7.y);
    }
    for (; j < end; j++) {
        int c = g_adj[j];
        uint2 pv = __ldg(&sv[(size_t)c * 32 + lane]);
        float2 q0 = __half22float2(*(__half2*)&pv.x), q1 = __half22float2(*(__half2*)&pv.y);
        acc.x += q0.x; acc.y += q0.y; acc.z += q1.x; acc.w += q1.y;
    }

    float d  = g_dinv[warp];
    float4 b = ((const float4*)bias)[lane];
    float4 o;
    o.x = acc.x * d + b.x;
    o.y = acc.y * d + b.y;
    o.z = acc.z * d + b.z;
    o.w = acc.w * d + b.w;
    ((float4*)out)[(size_t)warp * 32 + lane] = o;
}

// ---------------- launch ----------------
extern "C" void kernel_launch(void* const* d_in, const int* in_sizes, int n_in,
                              void* d_out, int out_size)
{
    const float* x    = (const float*)d_in[0];
    const void*  ei   = d_in[1];
    const float* w    = (const float*)d_in[2];
    const float* bias = (const float*)d_in[3];
    float*       out  = (float*)d_out;

    int n = in_sizes[0] / F;
    int e = in_sizes[1] / 2;

    int nb = (n + 1023) / 1024;

    detect_kernel<<<1, 256>>>((const unsigned int*)ei);

    init_deg_kernel<<<(n + 255) / 256, 256>>>(n);
    degree_kernel<<<(e + 255) / 256, 256>>>(ei, e);

    scan_local_kernel<<<nb, 256>>>(n);
    scan_bsums_kernel<<<1, 128>>>(nb);
    add_offsets_kernel<<<(n + 255) / 256, 256>>>(n, e);
    scatter_kernel<<<(e + 255) / 256, 256>>>(ei, e);

    size_t gemm_smem = (size_t)3 * 128 * APAD * sizeof(__half);  // 104448
    cudaFuncSetAttribute(gemm_tc_kernel,
                         cudaFuncAttributeMaxDynamicSharedMemorySize,
                         (int)gemm_smem);
    gemm_tc_kernel<<<(n + 127) / 128, 256, gemm_smem>>>(x, w, n);

    int agg_blocks = (n * 32 + 255) / 256;
    aggregate_kernel<<<agg_blocks, 256>>>(out, bias, n);
}